// round 10
// baseline (speedup 1.0000x reference)
#include <cuda_runtime.h>
#include <cuda_bf16.h>
#include <math.h>
#include <stdint.h>

// ---------------- problem dims ----------------
#define B_   8
#define L_   1024
#define D_   1024
#define E_   2048
#define S_   128
#define M_   (B_ * L_)        // 8192
#define NUV  (2 * E_ + S_)    // 4224

typedef unsigned short u16;

// ---------------- device scratch (bf16 hi/lo planes + fp32 where needed) ----
__device__ __align__(16) u16  g_xn_h [M_ * D_];
__device__ __align__(16) u16  g_xn_l [M_ * D_];
__device__ __align__(16) u16  g_w1_h [NUV * D_];
__device__ __align__(16) u16  g_w1_l [NUV * D_];
__device__ __align__(16) u16  g_ow_h [D_ * E_];
__device__ __align__(16) u16  g_ow_l [D_ * E_];
__device__ __align__(16) float g_u   [M_ * E_];
__device__ __align__(16) float g_v   [M_ * E_];
__device__ __align__(16) u16  g_vT_h [M_ * E_];
__device__ __align__(16) u16  g_vT_l [M_ * E_];
__device__ __align__(16) float g_base[M_ * S_];
__device__ __align__(16) u16  g_q_h  [M_ * S_];
__device__ __align__(16) u16  g_q_l  [M_ * S_];
__device__ __align__(16) u16  g_k_h  [M_ * S_];
__device__ __align__(16) u16  g_k_l  [M_ * S_];
__device__ __align__(16) u16  g_kn_h [(size_t)B_ * L_ * L_];
__device__ __align__(16) u16  g_kn_l [(size_t)B_ * L_ * L_];
__device__ __align__(16) u16  g_at_h [M_ * E_];
__device__ __align__(16) u16  g_at_l [M_ * E_];
__device__ float g_sin [L_ * 64];
__device__ float g_cos [L_ * 64];

// ---------------- helpers ----------------
__device__ __forceinline__ void split2(float x, float y, uint32_t& hi, uint32_t& lo) {
    float hx = __bfloat162float(__float2bfloat16_rn(x));
    float hy = __bfloat162float(__float2bfloat16_rn(y));
    asm("cvt.rn.bf16x2.f32 %0, %1, %2;" : "=r"(hi) : "f"(hy), "f"(hx));
    float lx = x - hx, ly = y - hy;
    asm("cvt.rn.bf16x2.f32 %0, %1, %2;" : "=r"(lo) : "f"(ly), "f"(lx));
}
__device__ __forceinline__ u16 bf16h(float x) {
    __nv_bfloat16 b = __float2bfloat16_rn(x);
    return *(u16*)&b;
}
__device__ __forceinline__ float bf16tof(u16 v) {
    __nv_bfloat16 b = *(__nv_bfloat16*)&v;
    return __bfloat162float(b);
}
__device__ __forceinline__ void mma_bf16(float* c, const uint32_t* a, const uint32_t* b) {
    asm volatile(
        "mma.sync.aligned.m16n8k16.row.col.f32.bf16.bf16.f32 "
        "{%0,%1,%2,%3}, {%4,%5,%6,%7}, {%8,%9}, {%0,%1,%2,%3};"
        : "+f"(c[0]), "+f"(c[1]), "+f"(c[2]), "+f"(c[3])
        : "r"(a[0]), "r"(a[1]), "r"(a[2]), "r"(a[3]), "r"(b[0]), "r"(b[1]));
}
__device__ __forceinline__ void ldsm_x4(uint32_t* r, uint32_t addr) {
    asm volatile("ldmatrix.sync.aligned.m8n8.x4.shared.b16 {%0,%1,%2,%3}, [%4];"
        : "=r"(r[0]), "=r"(r[1]), "=r"(r[2]), "=r"(r[3]) : "r"(addr));
}
__device__ __forceinline__ uint32_t smem_u32(const void* p) {
    uint32_t a;
    asm("{ .reg .u64 t; cvta.to.shared.u64 t, %1; cvt.u32.u64 %0, t; }" : "=r"(a) : "l"(p));
    return a;
}
__device__ __forceinline__ void cpa16(uint32_t s, const void* g) {
    asm volatile("cp.async.cg.shared.global [%0], [%1], 16;" :: "r"(s), "l"(g) : "memory");
}
#define CP_COMMIT() asm volatile("cp.async.commit_group;" ::: "memory")
#define CP_WAIT1()  asm volatile("cp.async.wait_group 1;" ::: "memory")
#define CP_WAIT0()  asm volatile("cp.async.wait_group 0;" ::: "memory")

#define STR 40                                // smem row stride (bf16 elems) = 80 B
#define PLANE_BYTES (128 * STR * 2)           // 10240
#define STAGE_BYTES (4 * PLANE_BYTES)         // 40960
#define SMEM_BYTES  (2 * STAGE_BYTES)         // 81920
#define OFF_AH 0
#define OFF_AL (PLANE_BYTES)
#define OFF_BH (2 * PLANE_BYTES)
#define OFF_BL (3 * PLANE_BYTES)

// ---------------- core: C[128x128] = A[128xK] * B[128xK]^T ------------------
// A/B given as bf16 hi+lo planes, row-major. 256 threads, 8 warps 2x4.
__device__ __forceinline__ void gemm_core_bf16(
    const u16* __restrict__ Ah, const u16* __restrict__ Al, int lda,
    const u16* __restrict__ Bh, const u16* __restrict__ Bl, int ldb,
    int K, float acc[4][4][4], char* smem)
{
    const int tid  = threadIdx.x;
    const int lane = tid & 31;
    const int wid  = tid >> 5;
    const int wm   = wid >> 2;
    const int wn   = wid & 3;
    uint32_t su = smem_u32(smem);

    // ldmatrix per-lane row/col select
    const int grp = lane >> 3, rr8 = lane & 7;
    const int rowsel = (grp & 1) * 8 + rr8;
    const uint32_t ksel = (uint32_t)((grp >> 1) * 16);   // k-halves byte offset
    const uint32_t asel = (uint32_t)((wm * 64 + rowsel) * 80) + ksel;
    const uint32_t bsel = (uint32_t)((wn * 32 + rowsel) * 80) + ksel;

    // cp.async per-thread load coords: 512 16B-chunks per plane, 2 per thread
    const int i0 = tid, i1 = tid + 256;
    const int r0 = i0 >> 2, c0 = (i0 & 3) * 8;
    const int r1 = i1 >> 2, c1 = (i1 & 3) * 8;
    const uint32_t so0 = (uint32_t)(r0 * (STR * 2) + (i0 & 3) * 16);
    const uint32_t so1 = (uint32_t)(r1 * (STR * 2) + (i1 & 3) * 16);

    const int NC = K >> 5;
    // prologue: chunk 0 -> stage 0
    {
        uint32_t st = su;
        cpa16(st + OFF_AH + so0, Ah + (size_t)r0 * lda + c0);
        cpa16(st + OFF_AH + so1, Ah + (size_t)r1 * lda + c1);
        cpa16(st + OFF_AL + so0, Al + (size_t)r0 * lda + c0);
        cpa16(st + OFF_AL + so1, Al + (size_t)r1 * lda + c1);
        cpa16(st + OFF_BH + so0, Bh + (size_t)r0 * ldb + c0);
        cpa16(st + OFF_BH + so1, Bh + (size_t)r1 * ldb + c1);
        cpa16(st + OFF_BL + so0, Bl + (size_t)r0 * ldb + c0);
        cpa16(st + OFF_BL + so1, Bl + (size_t)r1 * ldb + c1);
        CP_COMMIT();
    }

    for (int c = 0; c < NC; c++) {
        if (c + 1 < NC) {
            int k0 = (c + 1) * 32;
            uint32_t st = su + ((c + 1) & 1) * STAGE_BYTES;
            cpa16(st + OFF_AH + so0, Ah + (size_t)r0 * lda + k0 + c0);
            cpa16(st + OFF_AH + so1, Ah + (size_t)r1 * lda + k0 + c1);
            cpa16(st + OFF_AL + so0, Al + (size_t)r0 * lda + k0 + c0);
            cpa16(st + OFF_AL + so1, Al + (size_t)r1 * lda + k0 + c1);
            cpa16(st + OFF_BH + so0, Bh + (size_t)r0 * ldb + k0 + c0);
            cpa16(st + OFF_BH + so1, Bh + (size_t)r1 * ldb + k0 + c1);
            cpa16(st + OFF_BL + so0, Bl + (size_t)r0 * ldb + k0 + c0);
            cpa16(st + OFF_BL + so1, Bl + (size_t)r1 * ldb + k0 + c1);
            CP_COMMIT();
            CP_WAIT1();
        } else {
            CP_WAIT0();
        }
        __syncthreads();

        uint32_t stg = su + (c & 1) * STAGE_BYTES;

#pragma unroll
        for (int ks = 0; ks < 2; ks++) {
            const uint32_t kbb = (uint32_t)(ks * 32);    // k16 step = 32 bytes
            // load all B fragments first (16 regs)
            uint32_t Bh2[2][4], Bl2[2][4];
#pragma unroll
            for (int p = 0; p < 2; p++) {
                ldsm_x4(Bh2[p], stg + OFF_BH + bsel + (uint32_t)(p * 1280) + kbb);
                ldsm_x4(Bl2[p], stg + OFF_BL + bsel + (uint32_t)(p * 1280) + kbb);
            }
            // stream A per mt (8 regs live)
#pragma unroll
            for (int mt = 0; mt < 4; mt++) {
                uint32_t Ahf[4], Alf[4];
                ldsm_x4(Ahf, stg + OFF_AH + asel + (uint32_t)(mt * 1280) + kbb);
                ldsm_x4(Alf, stg + OFF_AL + asel + (uint32_t)(mt * 1280) + kbb);
#pragma unroll
                for (int nt = 0; nt < 4; nt++) {
                    uint32_t bhp[2] = { Bh2[nt >> 1][nt & 1], Bh2[nt >> 1][2 + (nt & 1)] };
                    uint32_t blp[2] = { Bl2[nt >> 1][nt & 1], Bl2[nt >> 1][2 + (nt & 1)] };
                    mma_bf16(acc[mt][nt], Ahf, bhp);
                    mma_bf16(acc[mt][nt], Ahf, blp);
                    mma_bf16(acc[mt][nt], Alf, bhp);
                }
            }
        }
        __syncthreads();
    }
}

// fragment (mt,nt,h) coords: row = wm*64+mt*16+g+h*8, col = wn*32+nt*8+tig*2 (+1)

// ---------------- GEMM1: uv = silu(xn @ uv_w^T), split u/v/base ------------
__global__ __launch_bounds__(256, 2)
void gemm1_tc() {
    extern __shared__ char smem[];
    float acc[4][4][4] = {};
    int bm = blockIdx.y, bn = blockIdx.x;
    gemm_core_bf16(g_xn_h + (size_t)bm * 128 * D_, g_xn_l + (size_t)bm * 128 * D_, D_,
                   g_w1_h + (size_t)bn * 128 * D_, g_w1_l + (size_t)bn * 128 * D_, D_,
                   D_, acc, smem);
    const int tid = threadIdx.x, wid = tid >> 5, lane = tid & 31;
    const int g = lane >> 2, tig = lane & 3, wm = wid >> 2, wn = wid & 3;
#pragma unroll
    for (int mt = 0; mt < 4; mt++) {
#pragma unroll
        for (int h = 0; h < 2; h++) {
            int m = bm * 128 + wm * 64 + mt * 16 + g + h * 8;
#pragma unroll
            for (int nt = 0; nt < 4; nt++) {
                int col = bn * 128 + wn * 32 + nt * 8 + tig * 2;
                float t0 = acc[mt][nt][h * 2 + 0];
                float t1 = acc[mt][nt][h * 2 + 1];
                float2 o;
                o.x = t0 / (1.0f + expf(-t0));
                o.y = t1 / (1.0f + expf(-t1));
                if (bn < 16)      *(float2*)(g_u + (size_t)m * E_ + col) = o;
                else if (bn < 32) *(float2*)(g_v + (size_t)m * E_ + (col - E_)) = o;
                else              *(float2*)(g_base + (size_t)m * S_ + (col - 2 * E_)) = o;
            }
        }
    }
}

// ---------------- GEMM2: kern = relu((qk + wrel)/sqrtS)^2 -> bf16 planes ---
__global__ __launch_bounds__(256, 2)
void gemm2_tc(const float* __restrict__ wrel) {
    extern __shared__ char smem[];
    float acc[4][4][4] = {};
    int b = blockIdx.z, bm = blockIdx.y, bn = blockIdx.x;
    size_t ao = (size_t)b * L_ * S_ + (size_t)bm * 128 * S_;
    size_t bo = (size_t)b * L_ * S_ + (size_t)bn * 128 * S_;
    gemm_core_bf16(g_q_h + ao, g_q_l + ao, S_, g_k_h + bo, g_k_l + bo, S_, S_, acc, smem);
    const int tid = threadIdx.x, wid = tid >> 5, lane = tid & 31;
    const int g = lane >> 2, tig = lane & 3, wm = wid >> 2, wn = wid & 3;
    const float inv_sqrtS = 0.08838834764831845f;
#pragma unroll
    for (int mt = 0; mt < 4; mt++) {
#pragma unroll
        for (int h = 0; h < 2; h++) {
            int mi = bm * 128 + wm * 64 + mt * 16 + g + h * 8;
            size_t rowoff = ((size_t)b * L_ + mi) * L_;
#pragma unroll
            for (int nt = 0; nt < 4; nt++) {
                int nj = bn * 128 + wn * 32 + nt * 8 + tig * 2;
                float t0 = (acc[mt][nt][h * 2 + 0] + wrel[nj - mi + (L_ - 1)]) * inv_sqrtS;
                float t1 = (acc[mt][nt][h * 2 + 1] + wrel[nj + 1 - mi + (L_ - 1)]) * inv_sqrtS;
                float r0 = fmaxf(t0, 0.0f), r1 = fmaxf(t1, 0.0f);
                uint32_t hh, ll;
                split2(r0 * r0, r1 * r1, hh, ll);
                *(uint32_t*)&g_kn_h[rowoff + nj] = hh;
                *(uint32_t*)&g_kn_l[rowoff + nj] = ll;
            }
        }
    }
}

// ---------------- GEMM3: attn = u * (kern @ v) -> bf16 planes --------------
__global__ __launch_bounds__(256, 2)
void gemm3_tc() {
    extern __shared__ char smem[];
    float acc[4][4][4] = {};
    int b = blockIdx.z, bm = blockIdx.y, bn = blockIdx.x;
    size_t ao = ((size_t)b * L_ + bm * 128) * L_;
    size_t bo = (size_t)b * E_ * L_ + (size_t)bn * 128 * L_;
    gemm_core_bf16(g_kn_h + ao, g_kn_l + ao, L_, g_vT_h + bo, g_vT_l + bo, L_, L_, acc, smem);
    const int tid = threadIdx.x, wid = tid >> 5, lane = tid & 31;
    const int g = lane >> 2, tig = lane & 3, wm = wid >> 2, wn = wid & 3;
#pragma unroll
    for (int mt = 0; mt < 4; mt++) {
#pragma unroll
        for (int h = 0; h < 2; h++) {
            int mi = bm * 128 + wm * 64 + mt * 16 + g + h * 8;
            size_t rowoff = ((size_t)b * L_ + mi) * E_;
#pragma unroll
            for (int nt = 0; nt < 4; nt++) {
                int nj = bn * 128 + wn * 32 + nt * 8 + tig * 2;
                float2 uu = *(const float2*)(g_u + rowoff + nj);
                uint32_t hh, ll;
                split2(uu.x * acc[mt][nt][h * 2 + 0], uu.y * acc[mt][nt][h * 2 + 1], hh, ll);
                *(uint32_t*)&g_at_h[rowoff + nj] = hh;
                *(uint32_t*)&g_at_l[rowoff + nj] = ll;
            }
        }
    }
}

// ---------------- GEMM4: y = attn @ o_w^T + x*res_scale --------------------
__global__ __launch_bounds__(256, 2)
void gemm4_tc(const float* __restrict__ x, const float* __restrict__ res_scale,
              float* __restrict__ out) {
    extern __shared__ char smem[];
    float acc[4][4][4] = {};
    int bm = blockIdx.y, bn = blockIdx.x;
    gemm_core_bf16(g_at_h + (size_t)bm * 128 * E_, g_at_l + (size_t)bm * 128 * E_, E_,
                   g_ow_h + (size_t)bn * 128 * E_, g_ow_l + (size_t)bn * 128 * E_, E_,
                   E_, acc, smem);
    const int tid = threadIdx.x, wid = tid >> 5, lane = tid & 31;
    const int g = lane >> 2, tig = lane & 3, wm = wid >> 2, wn = wid & 3;
#pragma unroll
    for (int mt = 0; mt < 4; mt++) {
#pragma unroll
        for (int h = 0; h < 2; h++) {
            int m = bm * 128 + wm * 64 + mt * 16 + g + h * 8;
#pragma unroll
            for (int nt = 0; nt < 4; nt++) {
                int d = bn * 128 + wn * 32 + nt * 8 + tig * 2;
                float2 xv = *(const float2*)(x + (size_t)m * D_ + d);
                float2 rs = *(const float2*)(res_scale + d);
                float2 o;
                o.x = xv.x * rs.x + acc[mt][nt][h * 2 + 0];
                o.y = xv.y * rs.y + acc[mt][nt][h * 2 + 1];
                *(float2*)(out + (size_t)m * D_ + d) = o;
            }
        }
    }
}

// ---------------- producers / elementwise ----------------
__global__ void rmsnorm_kernel(const float* __restrict__ x, const float* __restrict__ g) {
    int row = blockIdx.x;
    const float4* xr = (const float4*)(x + (size_t)row * D_);
    float4 v = xr[threadIdx.x];
    float s = v.x * v.x + v.y * v.y + v.z * v.z + v.w * v.w;
    __shared__ float red[256];
    red[threadIdx.x] = s;
    __syncthreads();
    for (int off = 128; off > 0; off >>= 1) {
        if (threadIdx.x < off) red[threadIdx.x] += red[threadIdx.x + off];
        __syncthreads();
    }
    __shared__ float sc;
    if (threadIdx.x == 0) {
        float norm = sqrtf(red[0]) * 0.03125f;
        sc = g[0] / fmaxf(norm, 1e-5f);
    }
    __syncthreads();
    float scale = sc;
    uint32_t h0, l0, h1, l1;
    split2(v.x * scale, v.y * scale, h0, l0);
    split2(v.z * scale, v.w * scale, h1, l1);
    size_t o = (size_t)row * D_ + threadIdx.x * 4;
    *(uint32_t*)&g_xn_h[o]     = h0;
    *(uint32_t*)&g_xn_h[o + 2] = h1;
    *(uint32_t*)&g_xn_l[o]     = l0;
    *(uint32_t*)&g_xn_l[o + 2] = l1;
}

__global__ void convert_pair_kernel(const float* __restrict__ src,
                                    u16* __restrict__ dh, u16* __restrict__ dl) {
    int i = (blockIdx.x * blockDim.x + threadIdx.x) * 2;
    float2 v = *(const float2*)(src + i);
    uint32_t h, l;
    split2(v.x, v.y, h, l);
    *(uint32_t*)&dh[i] = h;
    *(uint32_t*)&dl[i] = l;
}

__global__ void rope_table_kernel() {
    int idx = blockIdx.x * blockDim.x + threadIdx.x;
    int l = idx >> 6;
    int j = idx & 63;
    float inv_freq = (float)pow(10000.0, (double)j * (1.0 / 64.0));
    float a = __fmul_rn((float)l, inv_freq);
    g_sin[idx] = (float)sin((double)a);
    g_cos[idx] = (float)cos((double)a);
}

__global__ void rope_apply_kernel(const float* __restrict__ gamma, const float* __restrict__ beta) {
    int m = blockIdx.x;
    int s = threadIdx.x;
    int l = m & (L_ - 1);
    float b1 = g_base[m * S_ + s];
    float b2 = g_base[m * S_ + s + 64];
    float sn = g_sin[l * 64 + s];
    float cs = g_cos[l * 64 + s];
    float q1 = b1 * gamma[s]      + beta[s];
    float q2 = b2 * gamma[s + 64] + beta[s + 64];
    float qa = q1 * cs - q2 * sn;
    float qb = q2 * cs + q1 * sn;
    float k1 = b1 * gamma[128 + s]      + beta[128 + s];
    float k2 = b2 * gamma[128 + s + 64] + beta[128 + s + 64];
    float ka = k1 * cs - k2 * sn;
    float kb = k2 * cs + k1 * sn;
    int i0 = m * S_ + s, i1 = m * S_ + s + 64;
    u16 h;
    h = bf16h(qa); g_q_h[i0] = h; g_q_l[i0] = bf16h(qa - bf16tof(h));
    h = bf16h(qb); g_q_h[i1] = h; g_q_l[i1] = bf16h(qb - bf16tof(h));
    h = bf16h(ka); g_k_h[i0] = h; g_k_l[i0] = bf16h(ka - bf16tof(h));
    h = bf16h(kb); g_k_h[i1] = h; g_k_l[i1] = bf16h(kb - bf16tof(h));
}

__global__ void transpose_v_kernel() {  // g_v [b][l][e] -> vT planes [b][e][l]
    __shared__ float t[32][33];
    int b = blockIdx.z;
    int e0 = blockIdx.x * 32, l0 = blockIdx.y * 32;
#pragma unroll
    for (int i = 0; i < 32; i += 8)
        t[threadIdx.y + i][threadIdx.x] =
            g_v[((size_t)b * L_ + l0 + threadIdx.y + i) * E_ + e0 + threadIdx.x];
    __syncthreads();
#pragma unroll
    for (int i = 0; i < 32; i += 8) {
        float val = t[threadIdx.x][threadIdx.y + i];
        size_t o = ((size_t)b * E_ + e0 + threadIdx.y + i) * L_ + l0 + threadIdx.x;
        u16 h = bf16h(val);
        g_vT_h[o] = h;
        g_vT_l[o] = bf16h(val - bf16tof(h));
    }
}

// ---------------- launch ----------------
extern "C" void kernel_launch(void* const* d_in, const int* in_sizes, int n_in,
                              void* d_out, int out_size) {
    const float* x         = (const float*)d_in[0];
    const float* g         = (const float*)d_in[1];
    const float* uv_w      = (const float*)d_in[2];
    const float* gamma     = (const float*)d_in[3];
    const float* beta      = (const float*)d_in[4];
    const float* w_rel     = (const float*)d_in[5];
    const float* o_w       = (const float*)d_in[6];
    const float* res_scale = (const float*)d_in[7];
    float* out = (float*)d_out;

    static int attr_done = 0;
    if (!attr_done) {
        cudaFuncSetAttribute(gemm1_tc, cudaFuncAttributeMaxDynamicSharedMemorySize, SMEM_BYTES);
        cudaFuncSetAttribute(gemm2_tc, cudaFuncAttributeMaxDynamicSharedMemorySize, SMEM_BYTES);
        cudaFuncSetAttribute(gemm3_tc, cudaFuncAttributeMaxDynamicSharedMemorySize, SMEM_BYTES);
        cudaFuncSetAttribute(gemm4_tc, cudaFuncAttributeMaxDynamicSharedMemorySize, SMEM_BYTES);
        attr_done = 1;
    }

    u16* w1h; u16* w1l; u16* owh; u16* owl;
    cudaGetSymbolAddress((void**)&w1h, g_w1_h);
    cudaGetSymbolAddress((void**)&w1l, g_w1_l);
    cudaGetSymbolAddress((void**)&owh, g_ow_h);
    cudaGetSymbolAddress((void**)&owl, g_ow_l);

    rmsnorm_kernel<<<M_, 256>>>(x, g);
    rope_table_kernel<<<(L_ * 64) / 256, 256>>>();
    convert_pair_kernel<<<(NUV * D_) / 512, 256>>>(uv_w, w1h, w1l);
    convert_pair_kernel<<<(D_ * E_) / 512, 256>>>(o_w, owh, owl);
    gemm1_tc<<<dim3(33, 64), 256, SMEM_BYTES>>>();
    rope_apply_kernel<<<M_, 64>>>(gamma, beta);
    transpose_v_kernel<<<dim3(E_ / 32, L_ / 32, B_), dim3(32, 8)>>>();
    gemm2_tc<<<dim3(8, 8, 8), 256, SMEM_BYTES>>>(w_rel);
    gemm3_tc<<<dim3(16, 8, 8), 256, SMEM_BYTES>>>();
    gemm4_tc<<<dim3(8, 64), 256, SMEM_BYTES>>>(x, res_scale, out);
}

// round 12
// speedup vs baseline: 1.0055x; 1.0055x over previous
#include <cuda_runtime.h>
#include <cuda_bf16.h>
#include <math.h>
#include <stdint.h>

// ---------------- problem dims ----------------
#define B_   8
#define L_   1024
#define D_   1024
#define E_   2048
#define S_   128
#define M_   (B_ * L_)        // 8192
#define NUV  (2 * E_ + S_)    // 4224

typedef unsigned short u16;

// ---------------- device scratch (bf16 hi/lo planes + fp32 where needed) ----
__device__ __align__(16) u16  g_xn_h [M_ * D_];
__device__ __align__(16) u16  g_xn_l [M_ * D_];
__device__ __align__(16) u16  g_w1_h [NUV * D_];
__device__ __align__(16) u16  g_w1_l [NUV * D_];
__device__ __align__(16) u16  g_ow_h [D_ * E_];
__device__ __align__(16) u16  g_ow_l [D_ * E_];
__device__ __align__(16) float g_u   [M_ * E_];
__device__ __align__(16) float g_v   [M_ * E_];
__device__ __align__(16) u16  g_vT_h [M_ * E_];
__device__ __align__(16) u16  g_vT_l [M_ * E_];
__device__ __align__(16) float g_base[M_ * S_];
__device__ __align__(16) u16  g_q_h  [M_ * S_];
__device__ __align__(16) u16  g_q_l  [M_ * S_];
__device__ __align__(16) u16  g_k_h  [M_ * S_];
__device__ __align__(16) u16  g_k_l  [M_ * S_];
__device__ __align__(16) u16  g_kn_h [(size_t)B_ * L_ * L_];
__device__ __align__(16) u16  g_kn_l [(size_t)B_ * L_ * L_];
__device__ __align__(16) u16  g_at_h [M_ * E_];
__device__ __align__(16) u16  g_at_l [M_ * E_];
__device__ float g_sin [L_ * 64];
__device__ float g_cos [L_ * 64];

// ---------------- helpers ----------------
__device__ __forceinline__ void split2(float x, float y, uint32_t& hi, uint32_t& lo) {
    float hx = __bfloat162float(__float2bfloat16_rn(x));
    float hy = __bfloat162float(__float2bfloat16_rn(y));
    asm("cvt.rn.bf16x2.f32 %0, %1, %2;" : "=r"(hi) : "f"(hy), "f"(hx));
    float lx = x - hx, ly = y - hy;
    asm("cvt.rn.bf16x2.f32 %0, %1, %2;" : "=r"(lo) : "f"(ly), "f"(lx));
}
__device__ __forceinline__ u16 bf16h(float x) {
    __nv_bfloat16 b = __float2bfloat16_rn(x);
    return *(u16*)&b;
}
__device__ __forceinline__ float bf16tof(u16 v) {
    __nv_bfloat16 b = *(__nv_bfloat16*)&v;
    return __bfloat162float(b);
}
__device__ __forceinline__ void mma_bf16(float* c, const uint32_t* a, const uint32_t* b) {
    asm volatile(
        "mma.sync.aligned.m16n8k16.row.col.f32.bf16.bf16.f32 "
        "{%0,%1,%2,%3}, {%4,%5,%6,%7}, {%8,%9}, {%0,%1,%2,%3};"
        : "+f"(c[0]), "+f"(c[1]), "+f"(c[2]), "+f"(c[3])
        : "r"(a[0]), "r"(a[1]), "r"(a[2]), "r"(a[3]), "r"(b[0]), "r"(b[1]));
}
__device__ __forceinline__ void ldsm_x4(uint32_t* r, uint32_t addr) {
    asm volatile("ldmatrix.sync.aligned.m8n8.x4.shared.b16 {%0,%1,%2,%3}, [%4];"
        : "=r"(r[0]), "=r"(r[1]), "=r"(r[2]), "=r"(r[3]) : "r"(addr));
}
__device__ __forceinline__ uint32_t smem_u32(const void* p) {
    uint32_t a;
    asm("{ .reg .u64 t; cvta.to.shared.u64 t, %1; cvt.u32.u64 %0, t; }" : "=r"(a) : "l"(p));
    return a;
}
__device__ __forceinline__ void cpa16(uint32_t s, const void* g) {
    asm volatile("cp.async.cg.shared.global [%0], [%1], 16;" :: "r"(s), "l"(g) : "memory");
}
#define CP_COMMIT() asm volatile("cp.async.commit_group;" ::: "memory")
#define CP_WAIT1()  asm volatile("cp.async.wait_group 1;" ::: "memory")
#define CP_WAIT0()  asm volatile("cp.async.wait_group 0;" ::: "memory")

#define STR 40                                // smem row stride (bf16 elems) = 80 B
#define PLANE_BYTES (128 * STR * 2)           // 10240
#define STAGE_BYTES (4 * PLANE_BYTES)         // 40960
#define SMEM_BYTES  (2 * STAGE_BYTES)         // 81920
#define OFF_AH 0
#define OFF_AL (PLANE_BYTES)
#define OFF_BH (2 * PLANE_BYTES)
#define OFF_BL (3 * PLANE_BYTES)

// ---------------- core: C[128x128] = A[128xK] * B[128xK]^T ------------------
// A/B given as bf16 hi+lo planes, row-major. 256 threads, 8 warps 2x4.
__device__ __forceinline__ void gemm_core_bf16(
    const u16* __restrict__ Ah, const u16* __restrict__ Al, int lda,
    const u16* __restrict__ Bh, const u16* __restrict__ Bl, int ldb,
    int K, float acc[4][4][4], char* smem)
{
    const int tid  = threadIdx.x;
    const int lane = tid & 31;
    const int wid  = tid >> 5;
    const int wm   = wid >> 2;
    const int wn   = wid & 3;
    uint32_t su = smem_u32(smem);

    // ldmatrix per-lane row/col select
    const int grp = lane >> 3, rr8 = lane & 7;
    const int rowsel = (grp & 1) * 8 + rr8;
    const uint32_t ksel = (uint32_t)((grp >> 1) * 16);   // k-halves byte offset
    const uint32_t asel = (uint32_t)((wm * 64 + rowsel) * 80) + ksel;
    const uint32_t bsel = (uint32_t)((wn * 32 + rowsel) * 80) + ksel;

    // cp.async per-thread load coords: 512 16B-chunks per plane, 2 per thread
    const int i0 = tid, i1 = tid + 256;
    const int r0 = i0 >> 2, c0 = (i0 & 3) * 8;
    const int r1 = i1 >> 2, c1 = (i1 & 3) * 8;
    const uint32_t so0 = (uint32_t)(r0 * (STR * 2) + (i0 & 3) * 16);
    const uint32_t so1 = (uint32_t)(r1 * (STR * 2) + (i1 & 3) * 16);

    const int NC = K >> 5;
    // prologue: chunk 0 -> stage 0
    {
        uint32_t st = su;
        cpa16(st + OFF_AH + so0, Ah + (size_t)r0 * lda + c0);
        cpa16(st + OFF_AH + so1, Ah + (size_t)r1 * lda + c1);
        cpa16(st + OFF_AL + so0, Al + (size_t)r0 * lda + c0);
        cpa16(st + OFF_AL + so1, Al + (size_t)r1 * lda + c1);
        cpa16(st + OFF_BH + so0, Bh + (size_t)r0 * ldb + c0);
        cpa16(st + OFF_BH + so1, Bh + (size_t)r1 * ldb + c1);
        cpa16(st + OFF_BL + so0, Bl + (size_t)r0 * ldb + c0);
        cpa16(st + OFF_BL + so1, Bl + (size_t)r1 * ldb + c1);
        CP_COMMIT();
    }

    for (int c = 0; c < NC; c++) {
        if (c + 1 < NC) {
            int k0 = (c + 1) * 32;
            uint32_t st = su + ((c + 1) & 1) * STAGE_BYTES;
            cpa16(st + OFF_AH + so0, Ah + (size_t)r0 * lda + k0 + c0);
            cpa16(st + OFF_AH + so1, Ah + (size_t)r1 * lda + k0 + c1);
            cpa16(st + OFF_AL + so0, Al + (size_t)r0 * lda + k0 + c0);
            cpa16(st + OFF_AL + so1, Al + (size_t)r1 * lda + k0 + c1);
            cpa16(st + OFF_BH + so0, Bh + (size_t)r0 * ldb + k0 + c0);
            cpa16(st + OFF_BH + so1, Bh + (size_t)r1 * ldb + k0 + c1);
            cpa16(st + OFF_BL + so0, Bl + (size_t)r0 * ldb + k0 + c0);
            cpa16(st + OFF_BL + so1, Bl + (size_t)r1 * ldb + k0 + c1);
            CP_COMMIT();
            CP_WAIT1();
        } else {
            CP_WAIT0();
        }
        __syncthreads();

        uint32_t stg = su + (c & 1) * STAGE_BYTES;

#pragma unroll
        for (int ks = 0; ks < 2; ks++) {
            const uint32_t kbb = (uint32_t)(ks * 32);    // k16 step = 32 bytes
            // load all B fragments first (16 regs)
            uint32_t Bh2[2][4], Bl2[2][4];
#pragma unroll
            for (int p = 0; p < 2; p++) {
                ldsm_x4(Bh2[p], stg + OFF_BH + bsel + (uint32_t)(p * 1280) + kbb);
                ldsm_x4(Bl2[p], stg + OFF_BL + bsel + (uint32_t)(p * 1280) + kbb);
            }
            // stream A per mt (8 regs live)
#pragma unroll
            for (int mt = 0; mt < 4; mt++) {
                uint32_t Ahf[4], Alf[4];
                ldsm_x4(Ahf, stg + OFF_AH + asel + (uint32_t)(mt * 1280) + kbb);
                ldsm_x4(Alf, stg + OFF_AL + asel + (uint32_t)(mt * 1280) + kbb);
#pragma unroll
                for (int nt = 0; nt < 4; nt++) {
                    uint32_t bhp[2] = { Bh2[nt >> 1][nt & 1], Bh2[nt >> 1][2 + (nt & 1)] };
                    uint32_t blp[2] = { Bl2[nt >> 1][nt & 1], Bl2[nt >> 1][2 + (nt & 1)] };
                    mma_bf16(acc[mt][nt], Ahf, bhp);
                    mma_bf16(acc[mt][nt], Ahf, blp);
                    mma_bf16(acc[mt][nt], Alf, bhp);
                }
            }
        }
        __syncthreads();
    }
}

// fragment (mt,nt,h) coords: row = wm*64+mt*16+g+h*8, col = wn*32+nt*8+tig*2 (+1)

// ---------------- GEMM1: uv = silu(xn @ uv_w^T), split u/v/base ------------
__global__ __launch_bounds__(256)
void gemm1_tc() {
    extern __shared__ char smem[];
    float acc[4][4][4] = {};
    int bm = blockIdx.y, bn = blockIdx.x;
    gemm_core_bf16(g_xn_h + (size_t)bm * 128 * D_, g_xn_l + (size_t)bm * 128 * D_, D_,
                   g_w1_h + (size_t)bn * 128 * D_, g_w1_l + (size_t)bn * 128 * D_, D_,
                   D_, acc, smem);
    const int tid = threadIdx.x, wid = tid >> 5, lane = tid & 31;
    const int g = lane >> 2, tig = lane & 3, wm = wid >> 2, wn = wid & 3;
#pragma unroll
    for (int mt = 0; mt < 4; mt++) {
#pragma unroll
        for (int h = 0; h < 2; h++) {
            int m = bm * 128 + wm * 64 + mt * 16 + g + h * 8;
#pragma unroll
            for (int nt = 0; nt < 4; nt++) {
                int col = bn * 128 + wn * 32 + nt * 8 + tig * 2;
                float t0 = acc[mt][nt][h * 2 + 0];
                float t1 = acc[mt][nt][h * 2 + 1];
                float2 o;
                o.x = t0 / (1.0f + expf(-t0));
                o.y = t1 / (1.0f + expf(-t1));
                if (bn < 16)      *(float2*)(g_u + (size_t)m * E_ + col) = o;
                else if (bn < 32) *(float2*)(g_v + (size_t)m * E_ + (col - E_)) = o;
                else              *(float2*)(g_base + (size_t)m * S_ + (col - 2 * E_)) = o;
            }
        }
    }
}

// ---------------- GEMM2: kern = relu((qk + wrel)/sqrtS)^2 -> bf16 planes ---
__global__ __launch_bounds__(256)
void gemm2_tc(const float* __restrict__ wrel) {
    extern __shared__ char smem[];
    float acc[4][4][4] = {};
    int b = blockIdx.z, bm = blockIdx.y, bn = blockIdx.x;
    size_t ao = (size_t)b * L_ * S_ + (size_t)bm * 128 * S_;
    size_t bo = (size_t)b * L_ * S_ + (size_t)bn * 128 * S_;
    gemm_core_bf16(g_q_h + ao, g_q_l + ao, S_, g_k_h + bo, g_k_l + bo, S_, S_, acc, smem);
    const int tid = threadIdx.x, wid = tid >> 5, lane = tid & 31;
    const int g = lane >> 2, tig = lane & 3, wm = wid >> 2, wn = wid & 3;
    const float inv_sqrtS = 0.08838834764831845f;
#pragma unroll
    for (int mt = 0; mt < 4; mt++) {
#pragma unroll
        for (int h = 0; h < 2; h++) {
            int mi = bm * 128 + wm * 64 + mt * 16 + g + h * 8;
            size_t rowoff = ((size_t)b * L_ + mi) * L_;
#pragma unroll
            for (int nt = 0; nt < 4; nt++) {
                int nj = bn * 128 + wn * 32 + nt * 8 + tig * 2;
                float t0 = (acc[mt][nt][h * 2 + 0] + wrel[nj - mi + (L_ - 1)]) * inv_sqrtS;
                float t1 = (acc[mt][nt][h * 2 + 1] + wrel[nj + 1 - mi + (L_ - 1)]) * inv_sqrtS;
                float r0 = fmaxf(t0, 0.0f), r1 = fmaxf(t1, 0.0f);
                uint32_t hh, ll;
                split2(r0 * r0, r1 * r1, hh, ll);
                *(uint32_t*)&g_kn_h[rowoff + nj] = hh;
                *(uint32_t*)&g_kn_l[rowoff + nj] = ll;
            }
        }
    }
}

// ---------------- GEMM3: attn = u * (kern @ v) -> bf16 planes --------------
__global__ __launch_bounds__(256)
void gemm3_tc() {
    extern __shared__ char smem[];
    float acc[4][4][4] = {};
    int b = blockIdx.z, bm = blockIdx.y, bn = blockIdx.x;
    size_t ao = ((size_t)b * L_ + bm * 128) * L_;
    size_t bo = (size_t)b * E_ * L_ + (size_t)bn * 128 * L_;
    gemm_core_bf16(g_kn_h + ao, g_kn_l + ao, L_, g_vT_h + bo, g_vT_l + bo, L_, L_, acc, smem);
    const int tid = threadIdx.x, wid = tid >> 5, lane = tid & 31;
    const int g = lane >> 2, tig = lane & 3, wm = wid >> 2, wn = wid & 3;
#pragma unroll
    for (int mt = 0; mt < 4; mt++) {
#pragma unroll
        for (int h = 0; h < 2; h++) {
            int mi = bm * 128 + wm * 64 + mt * 16 + g + h * 8;
            size_t rowoff = ((size_t)b * L_ + mi) * E_;
#pragma unroll
            for (int nt = 0; nt < 4; nt++) {
                int nj = bn * 128 + wn * 32 + nt * 8 + tig * 2;
                float2 uu = *(const float2*)(g_u + rowoff + nj);
                uint32_t hh, ll;
                split2(uu.x * acc[mt][nt][h * 2 + 0], uu.y * acc[mt][nt][h * 2 + 1], hh, ll);
                *(uint32_t*)&g_at_h[rowoff + nj] = hh;
                *(uint32_t*)&g_at_l[rowoff + nj] = ll;
            }
        }
    }
}

// ---------------- GEMM4: y = attn @ o_w^T + x*res_scale --------------------
__global__ __launch_bounds__(256)
void gemm4_tc(const float* __restrict__ x, const float* __restrict__ res_scale,
              float* __restrict__ out) {
    extern __shared__ char smem[];
    float acc[4][4][4] = {};
    int bm = blockIdx.y, bn = blockIdx.x;
    gemm_core_bf16(g_at_h + (size_t)bm * 128 * E_, g_at_l + (size_t)bm * 128 * E_, E_,
                   g_ow_h + (size_t)bn * 128 * E_, g_ow_l + (size_t)bn * 128 * E_, E_,
                   E_, acc, smem);
    const int tid = threadIdx.x, wid = tid >> 5, lane = tid & 31;
    const int g = lane >> 2, tig = lane & 3, wm = wid >> 2, wn = wid & 3;
#pragma unroll
    for (int mt = 0; mt < 4; mt++) {
#pragma unroll
        for (int h = 0; h < 2; h++) {
            int m = bm * 128 + wm * 64 + mt * 16 + g + h * 8;
#pragma unroll
            for (int nt = 0; nt < 4; nt++) {
                int d = bn * 128 + wn * 32 + nt * 8 + tig * 2;
                float2 xv = *(const float2*)(x + (size_t)m * D_ + d);
                float2 rs = *(const float2*)(res_scale + d);
                float2 o;
                o.x = xv.x * rs.x + acc[mt][nt][h * 2 + 0];
                o.y = xv.y * rs.y + acc[mt][nt][h * 2 + 1];
                *(float2*)(out + (size_t)m * D_ + d) = o;
            }
        }
    }
}

// ---------------- producers / elementwise ----------------
__global__ void rmsnorm_kernel(const float* __restrict__ x, const float* __restrict__ g) {
    int row = blockIdx.x;
    const float4* xr = (const float4*)(x + (size_t)row * D_);
    float4 v = xr[threadIdx.x];
    float s = v.x * v.x + v.y * v.y + v.z * v.z + v.w * v.w;
    __shared__ float red[256];
    red[threadIdx.x] = s;
    __syncthreads();
    for (int off = 128; off > 0; off >>= 1) {
        if (threadIdx.x < off) red[threadIdx.x] += red[threadIdx.x + off];
        __syncthreads();
    }
    __shared__ float sc;
    if (threadIdx.x == 0) {
        float norm = sqrtf(red[0]) * 0.03125f;
        sc = g[0] / fmaxf(norm, 1e-5f);
    }
    __syncthreads();
    float scale = sc;
    uint32_t h0, l0, h1, l1;
    split2(v.x * scale, v.y * scale, h0, l0);
    split2(v.z * scale, v.w * scale, h1, l1);
    size_t o = (size_t)row * D_ + threadIdx.x * 4;
    *(uint32_t*)&g_xn_h[o]     = h0;
    *(uint32_t*)&g_xn_h[o + 2] = h1;
    *(uint32_t*)&g_xn_l[o]     = l0;
    *(uint32_t*)&g_xn_l[o + 2] = l1;
}

__global__ void convert_pair_kernel(const float* __restrict__ src,
                                    u16* __restrict__ dh, u16* __restrict__ dl) {
    int i = (blockIdx.x * blockDim.x + threadIdx.x) * 2;
    float2 v = *(const float2*)(src + i);
    uint32_t h, l;
    split2(v.x, v.y, h, l);
    *(uint32_t*)&dh[i] = h;
    *(uint32_t*)&dl[i] = l;
}

__global__ void rope_table_kernel() {
    int idx = blockIdx.x * blockDim.x + threadIdx.x;
    int l = idx >> 6;
    int j = idx & 63;
    float inv_freq = (float)pow(10000.0, (double)j * (1.0 / 64.0));
    float a = __fmul_rn((float)l, inv_freq);
    g_sin[idx] = (float)sin((double)a);
    g_cos[idx] = (float)cos((double)a);
}

__global__ void rope_apply_kernel(const float* __restrict__ gamma, const float* __restrict__ beta) {
    int m = blockIdx.x;
    int s = threadIdx.x;
    int l = m & (L_ - 1);
    float b1 = g_base[m * S_ + s];
    float b2 = g_base[m * S_ + s + 64];
    float sn = g_sin[l * 64 + s];
    float cs = g_cos[l * 64 + s];
    float q1 = b1 * gamma[s]      + beta[s];
    float q2 = b2 * gamma[s + 64] + beta[s + 64];
    float qa = q1 * cs - q2 * sn;
    float qb = q2 * cs + q1 * sn;
    float k1 = b1 * gamma[128 + s]      + beta[128 + s];
    float k2 = b2 * gamma[128 + s + 64] + beta[128 + s + 64];
    float ka = k1 * cs - k2 * sn;
    float kb = k2 * cs + k1 * sn;
    int i0 = m * S_ + s, i1 = m * S_ + s + 64;
    u16 h;
    h = bf16h(qa); g_q_h[i0] = h; g_q_l[i0] = bf16h(qa - bf16tof(h));
    h = bf16h(qb); g_q_h[i1] = h; g_q_l[i1] = bf16h(qb - bf16tof(h));
    h = bf16h(ka); g_k_h[i0] = h; g_k_l[i0] = bf16h(ka - bf16tof(h));
    h = bf16h(kb); g_k_h[i1] = h; g_k_l[i1] = bf16h(kb - bf16tof(h));
}

__global__ void transpose_v_kernel() {  // g_v [b][l][e] -> vT planes [b][e][l]
    __shared__ float t[32][33];
    int b = blockIdx.z;
    int e0 = blockIdx.x * 32, l0 = blockIdx.y * 32;
#pragma unroll
    for (int i = 0; i < 32; i += 8)
        t[threadIdx.y + i][threadIdx.x] =
            g_v[((size_t)b * L_ + l0 + threadIdx.y + i) * E_ + e0 + threadIdx.x];
    __syncthreads();
#pragma unroll
    for (int i = 0; i < 32; i += 8) {
        float val = t[threadIdx.x][threadIdx.y + i];
        size_t o = ((size_t)b * E_ + e0 + threadIdx.y + i) * L_ + l0 + threadIdx.x;
        u16 h = bf16h(val);
        g_vT_h[o] = h;
        g_vT_l[o] = bf16h(val - bf16tof(h));
    }
}

// ---------------- launch ----------------
extern "C" void kernel_launch(void* const* d_in, const int* in_sizes, int n_in,
                              void* d_out, int out_size) {
    const float* x         = (const float*)d_in[0];
    const float* g         = (const float*)d_in[1];
    const float* uv_w      = (const float*)d_in[2];
    const float* gamma     = (const float*)d_in[3];
    const float* beta      = (const float*)d_in[4];
    const float* w_rel     = (const float*)d_in[5];
    const float* o_w       = (const float*)d_in[6];
    const float* res_scale = (const float*)d_in[7];
    float* out = (float*)d_out;

    static int attr_done = 0;
    if (!attr_done) {
        cudaFuncSetAttribute(gemm1_tc, cudaFuncAttributeMaxDynamicSharedMemorySize, SMEM_BYTES);
        cudaFuncSetAttribute(gemm2_tc, cudaFuncAttributeMaxDynamicSharedMemorySize, SMEM_BYTES);
        cudaFuncSetAttribute(gemm3_tc, cudaFuncAttributeMaxDynamicSharedMemorySize, SMEM_BYTES);
        cudaFuncSetAttribute(gemm4_tc, cudaFuncAttributeMaxDynamicSharedMemorySize, SMEM_BYTES);
        attr_done = 1;
    }

    u16* w1h; u16* w1l; u16* owh; u16* owl;
    cudaGetSymbolAddress((void**)&w1h, g_w1_h);
    cudaGetSymbolAddress((void**)&w1l, g_w1_l);
    cudaGetSymbolAddress((void**)&owh, g_ow_h);
    cudaGetSymbolAddress((void**)&owl, g_ow_l);

    rmsnorm_kernel<<<M_, 256>>>(x, g);
    rope_table_kernel<<<(L_ * 64) / 256, 256>>>();
    convert_pair_kernel<<<(NUV * D_) / 512, 256>>>(uv_w, w1h, w1l);
    convert_pair_kernel<<<(D_ * E_) / 512, 256>>>(o_w, owh, owl);
    gemm1_tc<<<dim3(33, 64), 256, SMEM_BYTES>>>();
    rope_apply_kernel<<<M_, 64>>>(gamma, beta);
    transpose_v_kernel<<<dim3(E_ / 32, L_ / 32, B_), dim3(32, 8)>>>();
    gemm2_tc<<<dim3(8, 8, 8), 256, SMEM_BYTES>>>(w_rel);
    gemm3_tc<<<dim3(16, 8, 8), 256, SMEM_BYTES>>>();
    gemm4_tc<<<dim3(8, 64), 256, SMEM_BYTES>>>(x, res_scale, out);
}

// round 13
// speedup vs baseline: 1.0372x; 1.0315x over previous
#include <cuda_runtime.h>
#include <cuda_bf16.h>
#include <math.h>
#include <stdint.h>

// ---------------- problem dims ----------------
#define B_   8
#define L_   1024
#define D_   1024
#define E_   2048
#define S_   128
#define M_   (B_ * L_)        // 8192
#define NUV  (2 * E_ + S_)    // 4224

typedef unsigned short u16;

// ---------------- device scratch (bf16 hi/lo planes + fp32 where needed) ----
__device__ __align__(16) u16  g_xn_h [M_ * D_];
__device__ __align__(16) u16  g_xn_l [M_ * D_];
__device__ __align__(16) u16  g_w1_h [NUV * D_];
__device__ __align__(16) u16  g_w1_l [NUV * D_];
__device__ __align__(16) u16  g_ow_h [D_ * E_];
__device__ __align__(16) u16  g_ow_l [D_ * E_];
__device__ __align__(16) float g_u   [M_ * E_];
__device__ __align__(16) float g_v   [M_ * E_];
__device__ __align__(16) u16  g_vT_h [M_ * E_];
__device__ __align__(16) u16  g_vT_l [M_ * E_];
__device__ __align__(16) float g_base[M_ * S_];
__device__ __align__(16) u16  g_q_h  [M_ * S_];
__device__ __align__(16) u16  g_q_l  [M_ * S_];
__device__ __align__(16) u16  g_k_h  [M_ * S_];
__device__ __align__(16) u16  g_k_l  [M_ * S_];
__device__ __align__(16) u16  g_kn_h [(size_t)B_ * L_ * L_];
__device__ __align__(16) u16  g_kn_l [(size_t)B_ * L_ * L_];
__device__ __align__(16) u16  g_at_h [M_ * E_];
__device__ __align__(16) u16  g_at_l [M_ * E_];
__device__ float g_sin [L_ * 64];
__device__ float g_cos [L_ * 64];

// ---------------- helpers ----------------
__device__ __forceinline__ void split2(float x, float y, uint32_t& hi, uint32_t& lo) {
    float hx = __bfloat162float(__float2bfloat16_rn(x));
    float hy = __bfloat162float(__float2bfloat16_rn(y));
    asm("cvt.rn.bf16x2.f32 %0, %1, %2;" : "=r"(hi) : "f"(hy), "f"(hx));
    float lx = x - hx, ly = y - hy;
    asm("cvt.rn.bf16x2.f32 %0, %1, %2;" : "=r"(lo) : "f"(ly), "f"(lx));
}
__device__ __forceinline__ u16 bf16h(float x) {
    __nv_bfloat16 b = __float2bfloat16_rn(x);
    return *(u16*)&b;
}
__device__ __forceinline__ float bf16tof(u16 v) {
    __nv_bfloat16 b = *(__nv_bfloat16*)&v;
    return __bfloat162float(b);
}
__device__ __forceinline__ void mma_bf16(float* c, const uint32_t* a, const uint32_t* b) {
    asm volatile(
        "mma.sync.aligned.m16n8k16.row.col.f32.bf16.bf16.f32 "
        "{%0,%1,%2,%3}, {%4,%5,%6,%7}, {%8,%9}, {%0,%1,%2,%3};"
        : "+f"(c[0]), "+f"(c[1]), "+f"(c[2]), "+f"(c[3])
        : "r"(a[0]), "r"(a[1]), "r"(a[2]), "r"(a[3]), "r"(b[0]), "r"(b[1]));
}
__device__ __forceinline__ uint32_t smem_u32(const void* p) {
    uint32_t a;
    asm("{ .reg .u64 t; cvta.to.shared.u64 t, %1; cvt.u32.u64 %0, t; }" : "=r"(a) : "l"(p));
    return a;
}
__device__ __forceinline__ void cpa16(uint32_t s, const void* g) {
    asm volatile("cp.async.cg.shared.global [%0], [%1], 16;" :: "r"(s), "l"(g) : "memory");
}
#define CP_COMMIT() asm volatile("cp.async.commit_group;" ::: "memory")
#define CP_WAIT1()  asm volatile("cp.async.wait_group 1;" ::: "memory")
#define CP_WAIT0()  asm volatile("cp.async.wait_group 0;" ::: "memory")

// K-chunk = 64; smem row stride 72 bf16 elems = 144 B (conflict-free: banks (4g+tig)%32)
#define KC  64
#define STR 72
#define PLANE_BYTES (128 * STR * 2)           // 18432
#define STAGE_BYTES (4 * PLANE_BYTES)         // 73728
#define SMEM_BYTES  (2 * STAGE_BYTES)         // 147456
#define OFF_AH 0
#define OFF_AL (PLANE_BYTES)
#define OFF_BH (2 * PLANE_BYTES)
#define OFF_BL (3 * PLANE_BYTES)

// ---------------- core: C[128x128] = A[128xK] * B[128xK]^T ------------------
// A/B given as bf16 hi+lo planes, row-major. 256 threads, 8 warps 2x4.
// Scalar-LDS fragment preload (R6-validated), K-chunk 64 (4 k16 steps/barrier).
__device__ __forceinline__ void gemm_core_bf16(
    const u16* __restrict__ Ah, const u16* __restrict__ Al, int lda,
    const u16* __restrict__ Bh, const u16* __restrict__ Bl, int ldb,
    int K, float acc[4][4][4], char* smem)
{
    const int tid  = threadIdx.x;
    const int lane = tid & 31;
    const int wid  = tid >> 5;
    const int g    = lane >> 2;
    const int tig  = lane & 3;
    const int wm   = wid >> 2;
    const int wn   = wid & 3;
    uint32_t su = smem_u32(smem);

    // cp.async per-thread coords: 1024 16B-chunks per plane (128 rows x 8), 4 per thread
    int rr[4], cc[4];
    uint32_t so[4];
#pragma unroll
    for (int r = 0; r < 4; r++) {
        int idx = tid + 256 * r;
        rr[r] = idx >> 3;
        cc[r] = (idx & 7) * 8;                 // elem col
        so[r] = (uint32_t)(rr[r] * (STR * 2) + (idx & 7) * 16);
    }

    const int NC = K / KC;
    // prologue: chunk 0 -> stage 0
    {
        uint32_t st = su;
#pragma unroll
        for (int r = 0; r < 4; r++) {
            cpa16(st + OFF_AH + so[r], Ah + (size_t)rr[r] * lda + cc[r]);
            cpa16(st + OFF_AL + so[r], Al + (size_t)rr[r] * lda + cc[r]);
            cpa16(st + OFF_BH + so[r], Bh + (size_t)rr[r] * ldb + cc[r]);
            cpa16(st + OFF_BL + so[r], Bl + (size_t)rr[r] * ldb + cc[r]);
        }
        CP_COMMIT();
    }

    for (int c = 0; c < NC; c++) {
        if (c + 1 < NC) {
            int k0 = (c + 1) * KC;
            uint32_t st = su + ((c + 1) & 1) * STAGE_BYTES;
#pragma unroll
            for (int r = 0; r < 4; r++) {
                cpa16(st + OFF_AH + so[r], Ah + (size_t)rr[r] * lda + k0 + cc[r]);
                cpa16(st + OFF_AL + so[r], Al + (size_t)rr[r] * lda + k0 + cc[r]);
                cpa16(st + OFF_BH + so[r], Bh + (size_t)rr[r] * ldb + k0 + cc[r]);
                cpa16(st + OFF_BL + so[r], Bl + (size_t)rr[r] * ldb + k0 + cc[r]);
            }
            CP_COMMIT();
            CP_WAIT1();
        } else {
            CP_WAIT0();
        }
        __syncthreads();

        char* stg = smem + (c & 1) * STAGE_BYTES;
        const u16* sAh = (const u16*)(stg + OFF_AH);
        const u16* sAl = (const u16*)(stg + OFF_AL);
        const u16* sBh = (const u16*)(stg + OFF_BH);
        const u16* sBl = (const u16*)(stg + OFF_BL);

#pragma unroll
        for (int ks = 0; ks < KC / 16; ks++) {
            const int kb = ks * 16;
            uint32_t ah[4][4], al[4][4], bh[4][2], bl[4][2];
#pragma unroll
            for (int mt = 0; mt < 4; mt++) {
                int base = (wm * 64 + mt * 16 + g) * STR + kb + tig * 2;
                ah[mt][0] = *(uint32_t*)&sAh[base];
                ah[mt][1] = *(uint32_t*)&sAh[base + 8 * STR];
                ah[mt][2] = *(uint32_t*)&sAh[base + 8];
                ah[mt][3] = *(uint32_t*)&sAh[base + 8 * STR + 8];
                al[mt][0] = *(uint32_t*)&sAl[base];
                al[mt][1] = *(uint32_t*)&sAl[base + 8 * STR];
                al[mt][2] = *(uint32_t*)&sAl[base + 8];
                al[mt][3] = *(uint32_t*)&sAl[base + 8 * STR + 8];
            }
#pragma unroll
            for (int nt = 0; nt < 4; nt++) {
                int base = (wn * 32 + nt * 8 + g) * STR + kb + tig * 2;
                bh[nt][0] = *(uint32_t*)&sBh[base];
                bh[nt][1] = *(uint32_t*)&sBh[base + 8];
                bl[nt][0] = *(uint32_t*)&sBl[base];
                bl[nt][1] = *(uint32_t*)&sBl[base + 8];
            }
#pragma unroll
            for (int mt = 0; mt < 4; mt++)
#pragma unroll
                for (int nt = 0; nt < 4; nt++) {
                    mma_bf16(acc[mt][nt], ah[mt], bh[nt]);
                    mma_bf16(acc[mt][nt], ah[mt], bl[nt]);
                    mma_bf16(acc[mt][nt], al[mt], bh[nt]);
                }
        }
        __syncthreads();
    }
}

// fragment (mt,nt,h) coords: row = wm*64+mt*16+g+h*8, col = wn*32+nt*8+tig*2 (+1)

// ---------------- GEMM1: uv = silu(xn @ uv_w^T), split u/v/base ------------
__global__ __launch_bounds__(256)
void gemm1_tc() {
    extern __shared__ char smem[];
    float acc[4][4][4] = {};
    int bm = blockIdx.y, bn = blockIdx.x;
    gemm_core_bf16(g_xn_h + (size_t)bm * 128 * D_, g_xn_l + (size_t)bm * 128 * D_, D_,
                   g_w1_h + (size_t)bn * 128 * D_, g_w1_l + (size_t)bn * 128 * D_, D_,
                   D_, acc, smem);
    const int tid = threadIdx.x, wid = tid >> 5, lane = tid & 31;
    const int g = lane >> 2, tig = lane & 3, wm = wid >> 2, wn = wid & 3;
#pragma unroll
    for (int mt = 0; mt < 4; mt++) {
#pragma unroll
        for (int h = 0; h < 2; h++) {
            int m = bm * 128 + wm * 64 + mt * 16 + g + h * 8;
#pragma unroll
            for (int nt = 0; nt < 4; nt++) {
                int col = bn * 128 + wn * 32 + nt * 8 + tig * 2;
                float t0 = acc[mt][nt][h * 2 + 0];
                float t1 = acc[mt][nt][h * 2 + 1];
                float2 o;
                o.x = t0 / (1.0f + expf(-t0));
                o.y = t1 / (1.0f + expf(-t1));
                if (bn < 16)      *(float2*)(g_u + (size_t)m * E_ + col) = o;
                else if (bn < 32) *(float2*)(g_v + (size_t)m * E_ + (col - E_)) = o;
                else              *(float2*)(g_base + (size_t)m * S_ + (col - 2 * E_)) = o;
            }
        }
    }
}

// ---------------- GEMM2: kern = relu((qk + wrel)/sqrtS)^2 -> bf16 planes ---
__global__ __launch_bounds__(256)
void gemm2_tc(const float* __restrict__ wrel) {
    extern __shared__ char smem[];
    float acc[4][4][4] = {};
    int b = blockIdx.z, bm = blockIdx.y, bn = blockIdx.x;
    size_t ao = (size_t)b * L_ * S_ + (size_t)bm * 128 * S_;
    size_t bo = (size_t)b * L_ * S_ + (size_t)bn * 128 * S_;
    gemm_core_bf16(g_q_h + ao, g_q_l + ao, S_, g_k_h + bo, g_k_l + bo, S_, S_, acc, smem);
    const int tid = threadIdx.x, wid = tid >> 5, lane = tid & 31;
    const int g = lane >> 2, tig = lane & 3, wm = wid >> 2, wn = wid & 3;
    const float inv_sqrtS = 0.08838834764831845f;
#pragma unroll
    for (int mt = 0; mt < 4; mt++) {
#pragma unroll
        for (int h = 0; h < 2; h++) {
            int mi = bm * 128 + wm * 64 + mt * 16 + g + h * 8;
            size_t rowoff = ((size_t)b * L_ + mi) * L_;
#pragma unroll
            for (int nt = 0; nt < 4; nt++) {
                int nj = bn * 128 + wn * 32 + nt * 8 + tig * 2;
                float t0 = (acc[mt][nt][h * 2 + 0] + wrel[nj - mi + (L_ - 1)]) * inv_sqrtS;
                float t1 = (acc[mt][nt][h * 2 + 1] + wrel[nj + 1 - mi + (L_ - 1)]) * inv_sqrtS;
                float r0 = fmaxf(t0, 0.0f), r1 = fmaxf(t1, 0.0f);
                uint32_t hh, ll;
                split2(r0 * r0, r1 * r1, hh, ll);
                *(uint32_t*)&g_kn_h[rowoff + nj] = hh;
                *(uint32_t*)&g_kn_l[rowoff + nj] = ll;
            }
        }
    }
}

// ---------------- GEMM3: attn = u * (kern @ v) -> bf16 planes --------------
__global__ __launch_bounds__(256)
void gemm3_tc() {
    extern __shared__ char smem[];
    float acc[4][4][4] = {};
    int b = blockIdx.z, bm = blockIdx.y, bn = blockIdx.x;
    size_t ao = ((size_t)b * L_ + bm * 128) * L_;
    size_t bo = (size_t)b * E_ * L_ + (size_t)bn * 128 * L_;
    gemm_core_bf16(g_kn_h + ao, g_kn_l + ao, L_, g_vT_h + bo, g_vT_l + bo, L_, L_, acc, smem);
    const int tid = threadIdx.x, wid = tid >> 5, lane = tid & 31;
    const int g = lane >> 2, tig = lane & 3, wm = wid >> 2, wn = wid & 3;
#pragma unroll
    for (int mt = 0; mt < 4; mt++) {
#pragma unroll
        for (int h = 0; h < 2; h++) {
            int mi = bm * 128 + wm * 64 + mt * 16 + g + h * 8;
            size_t rowoff = ((size_t)b * L_ + mi) * E_;
#pragma unroll
            for (int nt = 0; nt < 4; nt++) {
                int nj = bn * 128 + wn * 32 + nt * 8 + tig * 2;
                float2 uu = *(const float2*)(g_u + rowoff + nj);
                uint32_t hh, ll;
                split2(uu.x * acc[mt][nt][h * 2 + 0], uu.y * acc[mt][nt][h * 2 + 1], hh, ll);
                *(uint32_t*)&g_at_h[rowoff + nj] = hh;
                *(uint32_t*)&g_at_l[rowoff + nj] = ll;
            }
        }
    }
}

// ---------------- GEMM4: y = attn @ o_w^T + x*res_scale --------------------
__global__ __launch_bounds__(256)
void gemm4_tc(const float* __restrict__ x, const float* __restrict__ res_scale,
              float* __restrict__ out) {
    extern __shared__ char smem[];
    float acc[4][4][4] = {};
    int bm = blockIdx.y, bn = blockIdx.x;
    gemm_core_bf16(g_at_h + (size_t)bm * 128 * E_, g_at_l + (size_t)bm * 128 * E_, E_,
                   g_ow_h + (size_t)bn * 128 * E_, g_ow_l + (size_t)bn * 128 * E_, E_,
                   E_, acc, smem);
    const int tid = threadIdx.x, wid = tid >> 5, lane = tid & 31;
    const int g = lane >> 2, tig = lane & 3, wm = wid >> 2, wn = wid & 3;
#pragma unroll
    for (int mt = 0; mt < 4; mt++) {
#pragma unroll
        for (int h = 0; h < 2; h++) {
            int m = bm * 128 + wm * 64 + mt * 16 + g + h * 8;
#pragma unroll
            for (int nt = 0; nt < 4; nt++) {
                int d = bn * 128 + wn * 32 + nt * 8 + tig * 2;
                float2 xv = *(const float2*)(x + (size_t)m * D_ + d);
                float2 rs = *(const float2*)(res_scale + d);
                float2 o;
                o.x = xv.x * rs.x + acc[mt][nt][h * 2 + 0];
                o.y = xv.y * rs.y + acc[mt][nt][h * 2 + 1];
                *(float2*)(out + (size_t)m * D_ + d) = o;
            }
        }
    }
}

// ---------------- producers / elementwise ----------------
__global__ void rmsnorm_kernel(const float* __restrict__ x, const float* __restrict__ g) {
    int row = blockIdx.x;
    const float4* xr = (const float4*)(x + (size_t)row * D_);
    float4 v = xr[threadIdx.x];
    float s = v.x * v.x + v.y * v.y + v.z * v.z + v.w * v.w;
    __shared__ float red[256];
    red[threadIdx.x] = s;
    __syncthreads();
    for (int off = 128; off > 0; off >>= 1) {
        if (threadIdx.x < off) red[threadIdx.x] += red[threadIdx.x + off];
        __syncthreads();
    }
    __shared__ float sc;
    if (threadIdx.x == 0) {
        float norm = sqrtf(red[0]) * 0.03125f;
        sc = g[0] / fmaxf(norm, 1e-5f);
    }
    __syncthreads();
    float scale = sc;
    uint32_t h0, l0, h1, l1;
    split2(v.x * scale, v.y * scale, h0, l0);
    split2(v.z * scale, v.w * scale, h1, l1);
    size_t o = (size_t)row * D_ + threadIdx.x * 4;
    *(uint32_t*)&g_xn_h[o]     = h0;
    *(uint32_t*)&g_xn_h[o + 2] = h1;
    *(uint32_t*)&g_xn_l[o]     = l0;
    *(uint32_t*)&g_xn_l[o + 2] = l1;
}

__global__ void convert_pair_kernel(const float* __restrict__ src,
                                    u16* __restrict__ dh, u16* __restrict__ dl) {
    int i = (blockIdx.x * blockDim.x + threadIdx.x) * 2;
    float2 v = *(const float2*)(src + i);
    uint32_t h, l;
    split2(v.x, v.y, h, l);
    *(uint32_t*)&dh[i] = h;
    *(uint32_t*)&dl[i] = l;
}

__global__ void rope_table_kernel() {
    int idx = blockIdx.x * blockDim.x + threadIdx.x;
    int l = idx >> 6;
    int j = idx & 63;
    float inv_freq = (float)pow(10000.0, (double)j * (1.0 / 64.0));
    float a = __fmul_rn((float)l, inv_freq);
    g_sin[idx] = (float)sin((double)a);
    g_cos[idx] = (float)cos((double)a);
}

__global__ void rope_apply_kernel(const float* __restrict__ gamma, const float* __restrict__ beta) {
    int m = blockIdx.x;
    int s = threadIdx.x;
    int l = m & (L_ - 1);
    float b1 = g_base[m * S_ + s];
    float b2 = g_base[m * S_ + s + 64];
    float sn = g_sin[l * 64 + s];
    float cs = g_cos[l * 64 + s];
    float q1 = b1 * gamma[s]      + beta[s];
    float q2 = b2 * gamma[s + 64] + beta[s + 64];
    float qa = q1 * cs - q2 * sn;
    float qb = q2 * cs + q1 * sn;
    float k1 = b1 * gamma[128 + s]      + beta[128 + s];
    float k2 = b2 * gamma[128 + s + 64] + beta[128 + s + 64];
    float ka = k1 * cs - k2 * sn;
    float kb = k2 * cs + k1 * sn;
    int i0 = m * S_ + s, i1 = m * S_ + s + 64;
    u16 h;
    h = bf16h(qa); g_q_h[i0] = h; g_q_l[i0] = bf16h(qa - bf16tof(h));
    h = bf16h(qb); g_q_h[i1] = h; g_q_l[i1] = bf16h(qb - bf16tof(h));
    h = bf16h(ka); g_k_h[i0] = h; g_k_l[i0] = bf16h(ka - bf16tof(h));
    h = bf16h(kb); g_k_h[i1] = h; g_k_l[i1] = bf16h(kb - bf16tof(h));
}

__global__ void transpose_v_kernel() {  // g_v [b][l][e] -> vT planes [b][e][l]
    __shared__ float t[32][33];
    int b = blockIdx.z;
    int e0 = blockIdx.x * 32, l0 = blockIdx.y * 32;
#pragma unroll
    for (int i = 0; i < 32; i += 8)
        t[threadIdx.y + i][threadIdx.x] =
            g_v[((size_t)b * L_ + l0 + threadIdx.y + i) * E_ + e0 + threadIdx.x];
    __syncthreads();
#pragma unroll
    for (int i = 0; i < 32; i += 8) {
        float val = t[threadIdx.x][threadIdx.y + i];
        size_t o = ((size_t)b * E_ + e0 + threadIdx.y + i) * L_ + l0 + threadIdx.x;
        u16 h = bf16h(val);
        g_vT_h[o] = h;
        g_vT_l[o] = bf16h(val - bf16tof(h));
    }
}

// ---------------- launch ----------------
extern "C" void kernel_launch(void* const* d_in, const int* in_sizes, int n_in,
                              void* d_out, int out_size) {
    const float* x         = (const float*)d_in[0];
    const float* g         = (const float*)d_in[1];
    const float* uv_w      = (const float*)d_in[2];
    const float* gamma     = (const float*)d_in[3];
    const float* beta      = (const float*)d_in[4];
    const float* w_rel     = (const float*)d_in[5];
    const float* o_w       = (const float*)d_in[6];
    const float* res_scale = (const float*)d_in[7];
    float* out = (float*)d_out;

    static int attr_done = 0;
    if (!attr_done) {
        cudaFuncSetAttribute(gemm1_tc, cudaFuncAttributeMaxDynamicSharedMemorySize, SMEM_BYTES);
        cudaFuncSetAttribute(gemm2_tc, cudaFuncAttributeMaxDynamicSharedMemorySize, SMEM_BYTES);
        cudaFuncSetAttribute(gemm3_tc, cudaFuncAttributeMaxDynamicSharedMemorySize, SMEM_BYTES);
        cudaFuncSetAttribute(gemm4_tc, cudaFuncAttributeMaxDynamicSharedMemorySize, SMEM_BYTES);
        attr_done = 1;
    }

    u16* w1h; u16* w1l; u16* owh; u16* owl;
    cudaGetSymbolAddress((void**)&w1h, g_w1_h);
    cudaGetSymbolAddress((void**)&w1l, g_w1_l);
    cudaGetSymbolAddress((void**)&owh, g_ow_h);
    cudaGetSymbolAddress((void**)&owl, g_ow_l);

    rmsnorm_kernel<<<M_, 256>>>(x, g);
    rope_table_kernel<<<(L_ * 64) / 256, 256>>>();
    convert_pair_kernel<<<(NUV * D_) / 512, 256>>>(uv_w, w1h, w1l);
    convert_pair_kernel<<<(D_ * E_) / 512, 256>>>(o_w, owh, owl);
    gemm1_tc<<<dim3(33, 64), 256, SMEM_BYTES>>>();
    rope_apply_kernel<<<M_, 64>>>(gamma, beta);
    transpose_v_kernel<<<dim3(E_ / 32, L_ / 32, B_), dim3(32, 8)>>>();
    gemm2_tc<<<dim3(8, 8, 8), 256, SMEM_BYTES>>>(w_rel);
    gemm3_tc<<<dim3(16, 8, 8), 256, SMEM_BYTES>>>();
    gemm4_tc<<<dim3(8, 64), 256, SMEM_BYTES>>>(x, res_scale, out);
}